// round 2
// baseline (speedup 1.0000x reference)
#include <cuda_runtime.h>
#include <math.h>

// ===== problem constants =====
#define Bn    32
#define Sn    2048
#define Dn    512
#define NCLSn 2
#define Hn    16
#define HDn   32
#define Rn    (Bn*Sn)      // 65536 rows
#define KS    19

// ===== scratch (static device globals; no allocations) =====
__device__ float g_kT[KS*Dn];          // summed mexican-hat kernel, [j][d]
__device__ float g_qflat[NCLSn*Dn];    // cls @ Wq
__device__ float g_Araw[Dn*32];        // score matrix (pre g-fold), [d][c]
__device__ float g_Ag[Dn*32];          // g-folded score matrix, [d][c]
__device__ float g_GA[32];
__device__ float g_BA[32];
__device__ float g_Wvp[Dn*Dn];         // g-folded Wv
__device__ float g_Gv[Dn];
__device__ float g_Bv[Dn];
__device__ float g_pos[Rn*Dn];         // 128 MB
__device__ float g_xnew[Rn*Dn];        // 128 MB
__device__ float g_mean[Rn];
__device__ float g_rstd[Rn];
__device__ float g_z[Bn*32*Dn];        // 2 MB   z[b][c][d]
__device__ float g_P[Bn*32];
__device__ float g_Q[Bn*32];
__device__ float g_o[Bn*NCLSn*Dn];

// ===== prep kernels =====
__global__ void k_prep_ksum(const float* __restrict__ w1,
                            const float* __restrict__ w2,
                            const float* __restrict__ w3) {
    int d = threadIdx.x;
    const float C = 0.8673250705840776f;  // 2/(sqrt(3)*pi^0.25)
    float out[KS];
    #pragma unroll
    for (int j = 0; j < KS; j++) out[j] = 0.f;
    const float* ws[3] = {w1, w2, w3};
    for (int w = 0; w < 3; w++) {
        float scale = ws[w][d];
        float shift = ws[w][Dn + d];
        float inv   = 1.f / scale;
        float amp   = C * rsqrtf(fabsf(scale));
        #pragma unroll
        for (int j = 0; j < KS; j++) {
            float xg = (float)(j - 9) - shift;
            float u  = xg * inv;
            out[j] += amp * (1.f - u * u) * expf(-0.5f * u * u);
        }
    }
    #pragma unroll
    for (int j = 0; j < KS; j++) g_kT[j * Dn + d] = out[j];
}

__global__ void k_prep_q(const float* __restrict__ cls, const float* __restrict__ Wq) {
    int idx = blockIdx.x * blockDim.x + threadIdx.x;   // 0..1023
    int n = idx >> 9, dp = idx & 511;
    float acc = 0.f;
    for (int d = 0; d < Dn; d++) acc += cls[n * Dn + d] * Wq[d * Dn + dp];
    g_qflat[n * Dn + dp] = acc;
}

__global__ void k_prep_A(const float* __restrict__ Wkv, const float* __restrict__ g1) {
    int d = blockIdx.x;
    int c = threadIdx.x;          // c = h*2 + n, 32 cols
    int h = c >> 1, n = c & 1;
    float acc = 0.f;
    #pragma unroll
    for (int hd = 0; hd < HDn; hd++)
        acc += Wkv[d * (2 * Dn) + h * HDn + hd] * g_qflat[n * Dn + h * HDn + hd];
    acc *= 0.17677669529663687f;  // HD^-0.5
    g_Araw[d * 32 + c] = acc;
    g_Ag[d * 32 + c]   = g1[d] * acc;
}

__global__ void k_prep_vec32(const float* __restrict__ b1) {
    int c = threadIdx.x;
    float ga = 0.f, ba = 0.f;
    for (int d = 0; d < Dn; d++) {
        ga += g_Ag[d * 32 + c];
        ba += b1[d] * g_Araw[d * 32 + c];
    }
    g_GA[c] = ga;
    g_BA[c] = ba;
}

__global__ void k_prep_wv(const float* __restrict__ Wkv, const float* __restrict__ g1) {
    int d = blockIdx.x, j = threadIdx.x;
    g_Wvp[d * Dn + j] = g1[d] * Wkv[d * (2 * Dn) + Dn + j];
}

__global__ void k_prep_vvec(const float* __restrict__ Wkv, const float* __restrict__ b1) {
    int j = threadIdx.x;
    float gv = 0.f, bv = 0.f;
    for (int d = 0; d < Dn; d++) {
        gv += g_Wvp[d * Dn + j];
        bv += b1[d] * Wkv[d * (2 * Dn) + Dn + j];
    }
    g_Gv[j] = gv;
    g_Bv[j] = bv;
}

// ===== depthwise conv (summed kernel), sliding window, 8 outputs/thread =====
__global__ void k_conv(const float* __restrict__ x) {
    int chunk = blockIdx.x;            // 0..8191
    int b  = chunk >> 8;               // 256 chunks per batch
    int s0 = (chunk & 255) * 8;
    int d  = threadIdx.x;
    const float* xb = x + (size_t)b * Sn * Dn;

    float w[KS];
    #pragma unroll
    for (int j = 0; j < KS; j++) w[j] = g_kT[j * Dn + d];

    float xv[26];
    #pragma unroll
    for (int l = 0; l < 26; l++) {
        int ss = s0 - 9 + l;
        xv[l] = ((unsigned)ss < (unsigned)Sn) ? xb[(size_t)ss * Dn + d] : 0.f;
    }
    float* pb = g_pos + ((size_t)(b * Sn + s0)) * Dn + d;
    #pragma unroll
    for (int o = 0; o < 8; o++) {
        float acc = 0.f;
        #pragma unroll
        for (int j = 0; j < KS; j++) acc += xv[o + j] * w[j];
        pb[(size_t)o * Dn] = acc;
    }
}

// ===== GEMM0: xnew = pos @ Wp1 + x + bp1. 128x128x8 tiles, double-buffered =====
__global__ void __launch_bounds__(256)
k_gemm0(const float* __restrict__ Wp1, const float* __restrict__ X,
        const float* __restrict__ bias) {
    __shared__ float As[2][8][128];
    __shared__ float Bs[2][8][128];
    int tid  = threadIdx.x;
    int brow = blockIdx.y * 128;
    int bcol = blockIdx.x * 128;
    int aRow = tid >> 1;
    int aK4  = (tid & 1) * 4;
    int bK   = tid >> 5;
    int bCol = (tid & 31) * 4;
    int ty = tid >> 4, tx = tid & 15;

    float acc[8][8];
    #pragma unroll
    for (int i = 0; i < 8; i++)
        #pragma unroll
        for (int j = 0; j < 8; j++) acc[i][j] = 0.f;

    const float* Ap = g_pos + (size_t)(brow + aRow) * Dn + aK4;
    const float* Wp = Wp1 + (size_t)bK * Dn + bcol + bCol;

    // prologue: load k0=0 into buffer 0
    {
        float4 a4 = *(const float4*)(Ap);
        float4 b4 = *(const float4*)(Wp);
        As[0][aK4 + 0][aRow] = a4.x;
        As[0][aK4 + 1][aRow] = a4.y;
        As[0][aK4 + 2][aRow] = a4.z;
        As[0][aK4 + 3][aRow] = a4.w;
        *(float4*)&Bs[0][bK][bCol] = b4;
    }
    __syncthreads();

    int buf = 0;
    for (int k0 = 8; k0 <= Dn; k0 += 8) {
        float4 a4n, b4n;
        bool more = (k0 < Dn);
        if (more) {
            a4n = *(const float4*)(Ap + k0);
            b4n = *(const float4*)(Wp + (size_t)k0 * Dn);
        }
        #pragma unroll
        for (int k = 0; k < 8; k++) {
            float ra[8], rb[8];
            *(float4*)&ra[0] = *(const float4*)&As[buf][k][ty * 8];
            *(float4*)&ra[4] = *(const float4*)&As[buf][k][ty * 8 + 4];
            *(float4*)&rb[0] = *(const float4*)&Bs[buf][k][tx * 8];
            *(float4*)&rb[4] = *(const float4*)&Bs[buf][k][tx * 8 + 4];
            #pragma unroll
            for (int i = 0; i < 8; i++)
                #pragma unroll
                for (int j = 0; j < 8; j++) acc[i][j] += ra[i] * rb[j];
        }
        if (more) {
            int nb = buf ^ 1;
            As[nb][aK4 + 0][aRow] = a4n.x;
            As[nb][aK4 + 1][aRow] = a4n.y;
            As[nb][aK4 + 2][aRow] = a4n.z;
            As[nb][aK4 + 3][aRow] = a4n.w;
            *(float4*)&Bs[nb][bK][bCol] = b4n;
        }
        __syncthreads();
        buf ^= 1;
    }

    #pragma unroll
    for (int i = 0; i < 8; i++) {
        int r  = brow + ty * 8 + i;
        int c0 = bcol + tx * 8;
        float o8[8];
        #pragma unroll
        for (int j = 0; j < 8; j++)
            o8[j] = acc[i][j] + X[(size_t)r * Dn + c0 + j] + bias[c0 + j];
        float* dst = g_xnew + (size_t)r * Dn + c0;
        *(float4*)dst       = *(float4*)&o8[0];
        *(float4*)(dst + 4) = *(float4*)&o8[4];
    }
}

// ===== per-row LN stats on xnew =====
__global__ void k_rowstats() {
    int gw   = (blockIdx.x * blockDim.x + threadIdx.x) >> 5;
    int lane = threadIdx.x & 31;
    const float* xr = g_xnew + (size_t)gw * Dn;
    float s = 0.f, ss = 0.f;
    #pragma unroll
    for (int d = lane; d < Dn; d += 32) {
        float v = xr[d];
        s += v; ss += v * v;
    }
    #pragma unroll
    for (int o = 16; o > 0; o >>= 1) {
        s  += __shfl_xor_sync(0xffffffff, s, o);
        ss += __shfl_xor_sync(0xffffffff, ss, o);
    }
    if (lane == 0) {
        float m   = s * (1.f / Dn);
        float var = ss * (1.f / Dn) - m * m;
        g_mean[gw] = m;
        g_rstd[gw] = rsqrtf(var + 1e-5f);
    }
}

// ===== scores as tiled GEMM: 256 rows x 32 cols per block =====
// attn[b,h,n,s] = sigmoid(rstd*(xnew·Ag - mean*GA) + BA - log(S))
__global__ void __launch_bounds__(256)
k_scores(float* __restrict__ attn_out) {
    __shared__ float Xs[32][260];   // [dd][r], padded
    __shared__ float As2[32][32];   // [dd][c]
    int t  = threadIdx.x;
    int R0 = blockIdx.x * 256;
    int rgrp = t & 31, cgrp = t >> 5;
    int r0 = rgrp * 8, c0 = cgrp * 4;

    float acc[8][4];
    #pragma unroll
    for (int i = 0; i < 8; i++)
        #pragma unroll
        for (int j = 0; j < 4; j++) acc[i][j] = 0.f;

    for (int dt = 0; dt < 16; dt++) {
        // load X tile transposed: 256 rows x 32 d
        #pragma unroll
        for (int i = 0; i < 8; i++) {
            int rr  = (t >> 3) + i * 32;
            int dd0 = (t & 7) * 4;
            float4 a4 = *(const float4*)(g_xnew + (size_t)(R0 + rr) * Dn + dt * 32 + dd0);
            Xs[dd0 + 0][rr] = a4.x;
            Xs[dd0 + 1][rr] = a4.y;
            Xs[dd0 + 2][rr] = a4.z;
            Xs[dd0 + 3][rr] = a4.w;
        }
        // load A tile
        {
            int dp = t >> 3, c4 = (t & 7) * 4;
            *(float4*)&As2[dp][c4] = *(const float4*)(g_Ag + (dt * 32 + dp) * 32 + c4);
        }
        __syncthreads();
        #pragma unroll
        for (int dd = 0; dd < 32; dd++) {
            float xa[8], ab[4];
            *(float4*)&xa[0] = *(const float4*)&Xs[dd][r0];
            *(float4*)&xa[4] = *(const float4*)&Xs[dd][r0 + 4];
            *(float4*)&ab[0] = *(const float4*)&As2[dd][c0];
            #pragma unroll
            for (int i = 0; i < 8; i++)
                #pragma unroll
                for (int j = 0; j < 4; j++) acc[i][j] += xa[i] * ab[j];
        }
        __syncthreads();
    }

    #pragma unroll
    for (int i = 0; i < 8; i++) {
        int gr = R0 + r0 + i;
        float rs = g_rstd[gr], mn = g_mean[gr];
        int b = gr >> 11, s = gr & 2047;
        #pragma unroll
        for (int j = 0; j < 4; j++) {
            int c = c0 + j;
            float sc = rs * (acc[i][j] - mn * g_GA[c]) + g_BA[c]
                       - 7.6246189861593985f;    // log(2048)
            float a = 1.f / (1.f + expf(-sc));
            attn_out[((size_t)(b * 32 + c)) * Sn + s] = a;
        }
    }
}

// ===== P,Q per (b,c): P = sum_s attn, Q = sum_s attn*rstd*mean =====
__global__ void k_pq(const float* __restrict__ attn) {
    int b = blockIdx.x;
    int t = threadIdx.x;
    int c = t >> 3, sg = t & 7;
    const float* ar = attn + ((size_t)(b * 32 + c)) * Sn;
    const float* rsd = g_rstd + b * Sn;
    const float* mnp = g_mean + b * Sn;
    float P = 0.f, Q = 0.f;
    for (int s = sg; s < Sn; s += 8) {
        float a = ar[s];
        P += a;
        Q += a * rsd[s] * mnp[s];
    }
    __shared__ float redP[256], redQ[256];
    redP[t] = P; redQ[t] = Q;
    __syncthreads();
    if (t < 32) {
        float p = 0.f, q = 0.f;
        #pragma unroll
        for (int k = 0; k < 8; k++) { p += redP[t * 8 + k]; q += redQ[t * 8 + k]; }
        g_P[b * 32 + t] = p;
        g_Q[b * 32 + t] = q;
    }
}

// ===== z[b,c,d] = sum_s attn[b,c,s]*rstd[b,s]*xnew[b,s,d] =====
__global__ void __launch_bounds__(256)
k_z(const float* __restrict__ attn) {
    __shared__ float a_sm[32][36];   // a*rstd tile [c][si]
    int t  = threadIdx.x;
    int d0 = blockIdx.x * 128;
    int b  = blockIdx.y;
    int cq = t >> 5;                 // 0..7 -> c0 = cq*4
    int dq = t & 31;                 // d = d0 + dq*4
    int c0 = cq * 4;
    int d  = d0 + dq * 4;

    float acc[4][4];
    #pragma unroll
    for (int j = 0; j < 4; j++)
        #pragma unroll
        for (int k = 0; k < 4; k++) acc[j][k] = 0.f;

    for (int s0 = 0; s0 < Sn; s0 += 32) {
        // load attn tile * rstd
        {
            int c  = t >> 3;
            int s4 = (t & 7) * 4;
            float4 a4 = *(const float4*)(attn + ((size_t)(b * 32 + c)) * Sn + s0 + s4);
            const float* rsd = g_rstd + b * Sn + s0 + s4;
            a4.x *= rsd[0]; a4.y *= rsd[1]; a4.z *= rsd[2]; a4.w *= rsd[3];
            *(float4*)&a_sm[c][s4] = a4;
        }
        __syncthreads();
        #pragma unroll 8
        for (int si = 0; si < 32; si++) {
            float4 xv = *(const float4*)(g_xnew + (size_t)(b * Sn + s0 + si) * Dn + d);
            #pragma unroll
            for (int j = 0; j < 4; j++) {
                float av = a_sm[c0 + j][si];
                acc[j][0] += av * xv.x;
                acc[j][1] += av * xv.y;
                acc[j][2] += av * xv.z;
                acc[j][3] += av * xv.w;
            }
        }
        __syncthreads();
    }
    #pragma unroll
    for (int j = 0; j < 4; j++) {
        float4 o4 = make_float4(acc[j][0], acc[j][1], acc[j][2], acc[j][3]);
        *(float4*)(g_z + (size_t)(b * 32 + c0 + j) * Dn + d) = o4;
    }
}

// ===== o[b,n,j] = z[b,c,:]·Wvp[:,j] - Q*Gv[j] + P*Bv[j], j = h*32+hd =====
__global__ void __launch_bounds__(256)
k_o() {
    __shared__ float zs[16][512];
    int b = blockIdx.x, n = blockIdx.y;
    int t = threadIdx.x;
    int hh = t >> 5;                 // handles h = hh and hh+8
    int hd = t & 31;

    for (int idx = t; idx < 16 * 512; idx += 256) {
        int h = idx >> 9, d = idx & 511;
        zs[h][d] = g_z[(size_t)(b * 32 + h * 2 + n) * Dn + d];
    }
    __syncthreads();

    #pragma unroll
    for (int hi = 0; hi < 2; hi++) {
        int h = hh + hi * 8;
        int j = h * HDn + hd;
        float acc = 0.f;
        for (int d = 0; d < Dn; d++)
            acc += zs[h][d] * g_Wvp[(size_t)d * Dn + j];
        int c = h * 2 + n;
        float o = acc - g_Q[b * 32 + c] * g_Gv[j] + g_P[b * 32 + c] * g_Bv[j];
        g_o[(b * NCLSn + n) * Dn + j] = o;
    }
}

// ===== head: proj + LN + MLP -> logits, one block per (b,n) =====
__global__ void __launch_bounds__(256)
k_head(const float* __restrict__ Wproj, const float* __restrict__ bproj,
       const float* __restrict__ g2, const float* __restrict__ b2,
       const float* __restrict__ Wc1, const float* __restrict__ bc1,
       const float* __restrict__ Wc2, const float* __restrict__ bc2,
       float* __restrict__ out) {
    int bn = blockIdx.x;   // 0..63
    int t  = threadIdx.x;
    __shared__ float row[Dn];
    __shared__ float tmp[Dn];
    __shared__ float red[256];

    row[t]       = g_o[bn * Dn + t];
    row[t + 256] = g_o[bn * Dn + t + 256];
    __syncthreads();

    float a0 = 0.f, a1 = 0.f;
    for (int d = 0; d < Dn; d++) {
        float rv = row[d];
        a0 += rv * Wproj[d * Dn + t];
        a1 += rv * Wproj[d * Dn + t + 256];
    }
    tmp[t]       = a0 + bproj[t];
    tmp[t + 256] = a1 + bproj[t + 256];
    __syncthreads();

    float ps  = tmp[t] + tmp[t + 256];
    float pss = tmp[t] * tmp[t] + tmp[t + 256] * tmp[t + 256];
    red[t] = ps; __syncthreads();
    for (int o = 128; o > 0; o >>= 1) { if (t < o) red[t] += red[t + o]; __syncthreads(); }
    float mean = red[0] * (1.f / Dn);
    __syncthreads();
    red[t] = pss; __syncthreads();
    for (int o = 128; o > 0; o >>= 1) { if (t < o) red[t] += red[t + o]; __syncthreads(); }
    float var  = red[0] * (1.f / Dn) - mean * mean;
    float rstd = rsqrtf(var + 1e-5f);
    __syncthreads();

    row[t]       = (tmp[t] - mean) * rstd * g2[t] + b2[t];
    row[t + 256] = (tmp[t + 256] - mean) * rstd * g2[t + 256] + b2[t + 256];
    __syncthreads();

    float c0 = 0.f, c1 = 0.f;
    for (int d = 0; d < Dn; d++) {
        float rv = row[d];
        c0 += rv * Wc1[d * Dn + t];
        c1 += rv * Wc1[d * Dn + t + 256];
    }
    c0 = fmaxf(c0 + bc1[t], 0.f);
    c1 = fmaxf(c1 + bc1[t + 256], 0.f);
    float part = c0 * Wc2[t] + c1 * Wc2[t + 256];
    red[t] = part; __syncthreads();
    for (int o = 128; o > 0; o >>= 1) { if (t < o) red[t] += red[t + o]; __syncthreads(); }
    if (t == 0) out[bn] = red[0] + bc2[0];
}

// ===== launch =====
extern "C" void kernel_launch(void* const* d_in, const int* in_sizes, int n_in,
                              void* d_out, int out_size) {
    const float* x     = (const float*)d_in[0];
    const float* wave1 = (const float*)d_in[1];
    const float* wave2 = (const float*)d_in[2];
    const float* wave3 = (const float*)d_in[3];
    const float* Wp1   = (const float*)d_in[4];
    const float* bp1   = (const float*)d_in[5];
    const float* cls   = (const float*)d_in[6];
    const float* ln1g  = (const float*)d_in[7];
    const float* ln1b  = (const float*)d_in[8];
    const float* Wq    = (const float*)d_in[9];
    const float* Wkv   = (const float*)d_in[10];
    const float* Wproj = (const float*)d_in[11];
    const float* bproj = (const float*)d_in[12];
    const float* ln2g  = (const float*)d_in[13];
    const float* ln2b  = (const float*)d_in[14];
    const float* Wc1   = (const float*)d_in[15];
    const float* bc1   = (const float*)d_in[16];
    const float* Wc2   = (const float*)d_in[17];
    const float* bc2   = (const float*)d_in[18];
    float* out = (float*)d_out;
    float* attn = out + Bn * NCLSn;   // logits first, then attn [B,H,NCLS,S]

    // small prep
    k_prep_ksum<<<1, 512>>>(wave1, wave2, wave3);
    k_prep_q<<<4, 256>>>(cls, Wq);
    k_prep_A<<<512, 32>>>(Wkv, ln1g);
    k_prep_vec32<<<1, 32>>>(ln1b);
    k_prep_wv<<<512, 512>>>(Wkv, ln1g);
    k_prep_vvec<<<1, 512>>>(Wkv, ln1b);

    // wavelet positional encoding
    k_conv<<<Rn / 8, 512>>>(x);
    k_gemm0<<<dim3(4, 512), 256>>>(Wp1, x, bp1);   // xnew = x + pos@Wp1 + bp1
    k_rowstats<<<8192, 256>>>();                    // LN stats

    // attention
    k_scores<<<256, 256>>>(attn);                   // attn (LN folded)
    k_pq<<<Bn, 256>>>(attn);
    k_z<<<dim3(4, Bn), 256>>>(attn);
    k_o<<<dim3(Bn, NCLSn), 256>>>();

    // head -> logits
    k_head<<<64, 256>>>(Wproj, bproj, ln2g, ln2b, Wc1, bc1, Wc2, bc2, out);
}

// round 3
// speedup vs baseline: 1.3740x; 1.3740x over previous
#include <cuda_runtime.h>
#include <math.h>

// ===== problem constants =====
#define Bn    32
#define Sn    2048
#define Dn    512
#define NCLSn 2
#define Hn    16
#define HDn   32
#define Rn    (Bn*Sn)      // 65536 rows
#define KS    19

// ===== scratch (static device globals; no allocations) =====
__device__ float g_kT[KS*Dn];          // summed mexican-hat kernel, [j][d]
__device__ float g_qflat[NCLSn*Dn];    // cls @ Wq
__device__ float g_Araw[Dn*32];        // score matrix (pre g-fold), [d][c]
__device__ float g_Ag[Dn*32];          // g-folded score matrix, [d][c]
__device__ float g_GA[32];
__device__ float g_BA[32];
__device__ float g_Wvp[Dn*Dn];         // g-folded Wv
__device__ float g_Gv[Dn];
__device__ float g_Bv[Dn];
__device__ float g_pos[Rn*Dn];         // 128 MB
__device__ float g_xnew[Rn*Dn];        // 128 MB
__device__ float g_mean[Rn];
__device__ float g_rstd[Rn];
__device__ float g_z[Bn*32*Dn];        // 2 MB   z[b][c][d]
__device__ float g_P[Bn*32];
__device__ float g_Q[Bn*32];
__device__ float g_o[Bn*NCLSn*Dn];

// ===== tf32 helpers =====
__device__ __forceinline__ unsigned f2tf(float x) {
    unsigned u;
    asm("cvt.rna.tf32.f32 %0, %1;" : "=r"(u) : "f"(x));
    return u;
}
__device__ __forceinline__ void mma_tf32(float* c, const unsigned* a, const unsigned* b) {
    asm volatile(
        "mma.sync.aligned.m16n8k8.row.col.f32.tf32.tf32.f32 "
        "{%0,%1,%2,%3},{%4,%5,%6,%7},{%8,%9},{%0,%1,%2,%3};"
        : "+f"(c[0]), "+f"(c[1]), "+f"(c[2]), "+f"(c[3])
        : "r"(a[0]), "r"(a[1]), "r"(a[2]), "r"(a[3]), "r"(b[0]), "r"(b[1]));
}

// ===== prep kernels =====
__global__ void k_prep_ksum(const float* __restrict__ w1,
                            const float* __restrict__ w2,
                            const float* __restrict__ w3) {
    int d = threadIdx.x;
    const float C = 0.8673250705840776f;  // 2/(sqrt(3)*pi^0.25)
    float out[KS];
    #pragma unroll
    for (int j = 0; j < KS; j++) out[j] = 0.f;
    const float* ws[3] = {w1, w2, w3};
    for (int w = 0; w < 3; w++) {
        float scale = ws[w][d];
        float shift = ws[w][Dn + d];
        float inv   = 1.f / scale;
        float amp   = C * rsqrtf(fabsf(scale));
        #pragma unroll
        for (int j = 0; j < KS; j++) {
            float xg = (float)(j - 9) - shift;
            float u  = xg * inv;
            out[j] += amp * (1.f - u * u) * expf(-0.5f * u * u);
        }
    }
    #pragma unroll
    for (int j = 0; j < KS; j++) g_kT[j * Dn + d] = out[j];
}

__global__ void k_prep_q(const float* __restrict__ cls, const float* __restrict__ Wq) {
    int idx = blockIdx.x * blockDim.x + threadIdx.x;   // 0..1023
    int n = idx >> 9, dp = idx & 511;
    float acc = 0.f;
    for (int d = 0; d < Dn; d++) acc += cls[n * Dn + d] * Wq[d * Dn + dp];
    g_qflat[n * Dn + dp] = acc;
}

__global__ void k_prep_A(const float* __restrict__ Wkv, const float* __restrict__ g1) {
    int d = blockIdx.x;
    int c = threadIdx.x;          // c = h*2 + n, 32 cols
    int h = c >> 1, n = c & 1;
    float acc = 0.f;
    #pragma unroll
    for (int hd = 0; hd < HDn; hd++)
        acc += Wkv[d * (2 * Dn) + h * HDn + hd] * g_qflat[n * Dn + h * HDn + hd];
    acc *= 0.17677669529663687f;  // HD^-0.5
    g_Araw[d * 32 + c] = acc;
    g_Ag[d * 32 + c]   = g1[d] * acc;
}

// wide column-sum over g_Ag / b1*g_Araw: 1024 threads, tree reduce
__global__ void k_prep_vec32(const float* __restrict__ b1) {
    __shared__ float sa[32][33];
    __shared__ float sb[32][33];
    int t  = threadIdx.x;
    int c  = t & 31;
    int dg = t >> 5;                // 0..31, each sums 16 rows
    float ga = 0.f, ba = 0.f;
    #pragma unroll
    for (int i = 0; i < 16; i++) {
        int d = dg * 16 + i;
        ga += g_Ag[d * 32 + c];
        ba += b1[d] * g_Araw[d * 32 + c];
    }
    sa[dg][c] = ga;
    sb[dg][c] = ba;
    __syncthreads();
    if (dg == 0) {
        float sga = 0.f, sba = 0.f;
        #pragma unroll
        for (int k = 0; k < 32; k++) { sga += sa[k][c]; sba += sb[k][c]; }
        g_GA[c] = sga;
        g_BA[c] = sba;
    }
}

__global__ void k_prep_wv(const float* __restrict__ Wkv, const float* __restrict__ g1) {
    int d = blockIdx.x, j = threadIdx.x;
    g_Wvp[d * Dn + j] = g1[d] * Wkv[d * (2 * Dn) + Dn + j];
}

// column sums of Wvp and b1*Wkv[:,Dn:]: 4 blocks x 128 threads, coalesced
__global__ void k_prep_vvec(const float* __restrict__ Wkv, const float* __restrict__ b1) {
    int j = blockIdx.x * 128 + threadIdx.x;
    float gv = 0.f, bv = 0.f;
    #pragma unroll 4
    for (int d = 0; d < Dn; d++) {
        gv += g_Wvp[d * Dn + j];
        bv += b1[d] * Wkv[d * (2 * Dn) + Dn + j];
    }
    g_Gv[j] = gv;
    g_Bv[j] = bv;
}

// ===== depthwise conv (summed kernel), sliding window, 8 outputs/thread =====
__global__ void k_conv(const float* __restrict__ x) {
    int chunk = blockIdx.x;            // 0..8191
    int b  = chunk >> 8;               // 256 chunks per batch
    int s0 = (chunk & 255) * 8;
    int d  = threadIdx.x;
    const float* xb = x + (size_t)b * Sn * Dn;

    float w[KS];
    #pragma unroll
    for (int j = 0; j < KS; j++) w[j] = g_kT[j * Dn + d];

    float xv[26];
    #pragma unroll
    for (int l = 0; l < 26; l++) {
        int ss = s0 - 9 + l;
        xv[l] = ((unsigned)ss < (unsigned)Sn) ? xb[(size_t)ss * Dn + d] : 0.f;
    }
    float* pb = g_pos + ((size_t)(b * Sn + s0)) * Dn + d;
    #pragma unroll
    for (int o = 0; o < 8; o++) {
        float acc = 0.f;
        #pragma unroll
        for (int j = 0; j < KS; j++) acc += xv[o + j] * w[j];
        pb[(size_t)o * Dn] = acc;
    }
}

// ===== GEMM0 (tf32 tensor cores): xnew = pos @ Wp1 + x + bp1 =====
// 128x128 block tile, K-tile 16, 8 warps (64x32 warp tile), mma.m16n8k8
#define SPAD 136
__global__ void __launch_bounds__(256)
k_gemm0(const float* __restrict__ Wp1, const float* __restrict__ X,
        const float* __restrict__ bias) {
    __shared__ unsigned As[2][16][SPAD];   // [k][m]
    __shared__ unsigned Bs[2][16][SPAD];   // [k][n]
    int t    = threadIdx.x;
    int brow = blockIdx.y * 128;
    int bcol = blockIdx.x * 128;
    int lane = t & 31, warp = t >> 5;
    int g    = lane >> 2, tig = lane & 3;
    int m0w  = (warp >> 2) * 64;
    int n0w  = (warp & 3) * 32;

    int arow = t >> 1, akh = (t & 1) * 8;       // A: row, k-half
    int bkr  = t >> 4, bn8 = (t & 15) * 8;      // B: k-row, n-offset

    const float* pA = g_pos + (size_t)(brow + arow) * Dn + akh;
    const float* pB = Wp1 + (size_t)bkr * Dn + bcol + bn8;

    float acc[4][4][4];
    #pragma unroll
    for (int i = 0; i < 4; i++)
        #pragma unroll
        for (int j = 0; j < 4; j++)
            #pragma unroll
            for (int k = 0; k < 4; k++) acc[i][j][k] = 0.f;

    // prologue: tile 0
    {
        float4 A0 = *(const float4*)(pA);
        float4 A1 = *(const float4*)(pA + 4);
        float4 B0 = *(const float4*)(pB);
        float4 B1 = *(const float4*)(pB + 4);
        As[0][akh + 0][arow] = f2tf(A0.x);
        As[0][akh + 1][arow] = f2tf(A0.y);
        As[0][akh + 2][arow] = f2tf(A0.z);
        As[0][akh + 3][arow] = f2tf(A0.w);
        As[0][akh + 4][arow] = f2tf(A1.x);
        As[0][akh + 5][arow] = f2tf(A1.y);
        As[0][akh + 6][arow] = f2tf(A1.z);
        As[0][akh + 7][arow] = f2tf(A1.w);
        Bs[0][bkr][bn8 + 0] = f2tf(B0.x);
        Bs[0][bkr][bn8 + 1] = f2tf(B0.y);
        Bs[0][bkr][bn8 + 2] = f2tf(B0.z);
        Bs[0][bkr][bn8 + 3] = f2tf(B0.w);
        Bs[0][bkr][bn8 + 4] = f2tf(B1.x);
        Bs[0][bkr][bn8 + 5] = f2tf(B1.y);
        Bs[0][bkr][bn8 + 6] = f2tf(B1.z);
        Bs[0][bkr][bn8 + 7] = f2tf(B1.w);
    }
    __syncthreads();

    int buf = 0;
    for (int kt = 1; kt <= 32; kt++) {
        bool more = (kt < 32);
        float4 A0, A1, B0, B1;
        if (more) {
            int k0 = kt * 16;
            A0 = *(const float4*)(pA + k0);
            A1 = *(const float4*)(pA + k0 + 4);
            B0 = *(const float4*)(pB + (size_t)k0 * Dn);
            B1 = *(const float4*)(pB + (size_t)k0 * Dn + 4);
        }
        // compute on buf: 2 k-steps of 8
        #pragma unroll
        for (int ks = 0; ks < 16; ks += 8) {
            unsigned a[4][4], b[4][2];
            #pragma unroll
            for (int i = 0; i < 4; i++) {
                int m = m0w + 16 * i + g;
                a[i][0] = As[buf][ks + tig][m];
                a[i][1] = As[buf][ks + tig][m + 8];
                a[i][2] = As[buf][ks + tig + 4][m];
                a[i][3] = As[buf][ks + tig + 4][m + 8];
            }
            #pragma unroll
            for (int j = 0; j < 4; j++) {
                int n = n0w + 8 * j + g;
                b[j][0] = Bs[buf][ks + tig][n];
                b[j][1] = Bs[buf][ks + tig + 4][n];
            }
            #pragma unroll
            for (int i = 0; i < 4; i++)
                #pragma unroll
                for (int j = 0; j < 4; j++)
                    mma_tf32(acc[i][j], a[i], b[j]);
        }
        if (more) {
            int nb = buf ^ 1;
            As[nb][akh + 0][arow] = f2tf(A0.x);
            As[nb][akh + 1][arow] = f2tf(A0.y);
            As[nb][akh + 2][arow] = f2tf(A0.z);
            As[nb][akh + 3][arow] = f2tf(A0.w);
            As[nb][akh + 4][arow] = f2tf(A1.x);
            As[nb][akh + 5][arow] = f2tf(A1.y);
            As[nb][akh + 6][arow] = f2tf(A1.z);
            As[nb][akh + 7][arow] = f2tf(A1.w);
            Bs[nb][bkr][bn8 + 0] = f2tf(B0.x);
            Bs[nb][bkr][bn8 + 1] = f2tf(B0.y);
            Bs[nb][bkr][bn8 + 2] = f2tf(B0.z);
            Bs[nb][bkr][bn8 + 3] = f2tf(B0.w);
            Bs[nb][bkr][bn8 + 4] = f2tf(B1.x);
            Bs[nb][bkr][bn8 + 5] = f2tf(B1.y);
            Bs[nb][bkr][bn8 + 6] = f2tf(B1.z);
            Bs[nb][bkr][bn8 + 7] = f2tf(B1.w);
        }
        __syncthreads();
        buf ^= 1;
    }

    // epilogue: out = acc + X + bias
    #pragma unroll
    for (int i = 0; i < 4; i++) {
        #pragma unroll
        for (int j = 0; j < 4; j++) {
            int r1 = brow + m0w + 16 * i + g;
            int r2 = r1 + 8;
            int cc = bcol + n0w + 8 * j + 2 * tig;
            float2 bb = *(const float2*)(bias + cc);
            float2 x1 = *(const float2*)(X + (size_t)r1 * Dn + cc);
            float2 o1 = make_float2(acc[i][j][0] + x1.x + bb.x,
                                    acc[i][j][1] + x1.y + bb.y);
            *(float2*)(g_xnew + (size_t)r1 * Dn + cc) = o1;
            float2 x2 = *(const float2*)(X + (size_t)r2 * Dn + cc);
            float2 o2 = make_float2(acc[i][j][2] + x2.x + bb.x,
                                    acc[i][j][3] + x2.y + bb.y);
            *(float2*)(g_xnew + (size_t)r2 * Dn + cc) = o2;
        }
    }
}

// ===== per-row LN stats on xnew =====
__global__ void k_rowstats() {
    int gw   = (blockIdx.x * blockDim.x + threadIdx.x) >> 5;
    int lane = threadIdx.x & 31;
    const float* xr = g_xnew + (size_t)gw * Dn;
    float s = 0.f, ss = 0.f;
    #pragma unroll
    for (int d = lane; d < Dn; d += 32) {
        float v = xr[d];
        s += v; ss += v * v;
    }
    #pragma unroll
    for (int o = 16; o > 0; o >>= 1) {
        s  += __shfl_xor_sync(0xffffffff, s, o);
        ss += __shfl_xor_sync(0xffffffff, ss, o);
    }
    if (lane == 0) {
        float m   = s * (1.f / Dn);
        float var = ss * (1.f / Dn) - m * m;
        g_mean[gw] = m;
        g_rstd[gw] = rsqrtf(var + 1e-5f);
    }
}

// ===== scores as tiled GEMM: 256 rows x 32 cols per block =====
// attn[b,h,n,s] = sigmoid(rstd*(xnew·Ag - mean*GA) + BA - log(S))
__global__ void __launch_bounds__(256)
k_scores(float* __restrict__ attn_out) {
    __shared__ float Xs[32][260];   // [dd][r], padded
    __shared__ float As2[32][32];   // [dd][c]
    int t  = threadIdx.x;
    int R0 = blockIdx.x * 256;
    int rgrp = t & 31, cgrp = t >> 5;
    int r0 = rgrp * 8, c0 = cgrp * 4;

    float acc[8][4];
    #pragma unroll
    for (int i = 0; i < 8; i++)
        #pragma unroll
        for (int j = 0; j < 4; j++) acc[i][j] = 0.f;

    for (int dt = 0; dt < 16; dt++) {
        #pragma unroll
        for (int i = 0; i < 8; i++) {
            int rr  = (t >> 3) + i * 32;
            int dd0 = (t & 7) * 4;
            float4 a4 = *(const float4*)(g_xnew + (size_t)(R0 + rr) * Dn + dt * 32 + dd0);
            Xs[dd0 + 0][rr] = a4.x;
            Xs[dd0 + 1][rr] = a4.y;
            Xs[dd0 + 2][rr] = a4.z;
            Xs[dd0 + 3][rr] = a4.w;
        }
        {
            int dp = t >> 3, c4 = (t & 7) * 4;
            *(float4*)&As2[dp][c4] = *(const float4*)(g_Ag + (dt * 32 + dp) * 32 + c4);
        }
        __syncthreads();
        #pragma unroll
        for (int dd = 0; dd < 32; dd++) {
            float xa[8], ab[4];
            *(float4*)&xa[0] = *(const float4*)&Xs[dd][r0];
            *(float4*)&xa[4] = *(const float4*)&Xs[dd][r0 + 4];
            *(float4*)&ab[0] = *(const float4*)&As2[dd][c0];
            #pragma unroll
            for (int i = 0; i < 8; i++)
                #pragma unroll
                for (int j = 0; j < 4; j++) acc[i][j] += xa[i] * ab[j];
        }
        __syncthreads();
    }

    #pragma unroll
    for (int i = 0; i < 8; i++) {
        int gr = R0 + r0 + i;
        float rs = g_rstd[gr], mn = g_mean[gr];
        int b = gr >> 11, s = gr & 2047;
        #pragma unroll
        for (int j = 0; j < 4; j++) {
            int c = c0 + j;
            float sc = rs * (acc[i][j] - mn * g_GA[c]) + g_BA[c]
                       - 7.6246189861593985f;    // log(2048)
            float a = 1.f / (1.f + expf(-sc));
            attn_out[((size_t)(b * 32 + c)) * Sn + s] = a;
        }
    }
}

// ===== P,Q per (b,c): P = sum_s attn, Q = sum_s attn*rstd*mean =====
__global__ void k_pq(const float* __restrict__ attn) {
    int b = blockIdx.x;
    int t = threadIdx.x;
    int c = t >> 3, sg = t & 7;
    const float* ar = attn + ((size_t)(b * 32 + c)) * Sn;
    const float* rsd = g_rstd + b * Sn;
    const float* mnp = g_mean + b * Sn;
    float P = 0.f, Q = 0.f;
    for (int s = sg; s < Sn; s += 8) {
        float a = ar[s];
        P += a;
        Q += a * rsd[s] * mnp[s];
    }
    __shared__ float redP[256], redQ[256];
    redP[t] = P; redQ[t] = Q;
    __syncthreads();
    if (t < 32) {
        float p = 0.f, q = 0.f;
        #pragma unroll
        for (int k = 0; k < 8; k++) { p += redP[t * 8 + k]; q += redQ[t * 8 + k]; }
        g_P[b * 32 + t] = p;
        g_Q[b * 32 + t] = q;
    }
}

// ===== z[b,c,d] = sum_s attn[b,c,s]*rstd[b,s]*xnew[b,s,d] =====
__global__ void __launch_bounds__(256)
k_z(const float* __restrict__ attn) {
    __shared__ float a_sm[32][36];   // a*rstd tile [c][si]
    int t  = threadIdx.x;
    int d0 = blockIdx.x * 128;
    int b  = blockIdx.y;
    int cq = t >> 5;                 // 0..7 -> c0 = cq*4
    int dq = t & 31;                 // d = d0 + dq*4
    int c0 = cq * 4;
    int d  = d0 + dq * 4;

    float acc[4][4];
    #pragma unroll
    for (int j = 0; j < 4; j++)
        #pragma unroll
        for (int k = 0; k < 4; k++) acc[j][k] = 0.f;

    for (int s0 = 0; s0 < Sn; s0 += 32) {
        {
            int c  = t >> 3;
            int s4 = (t & 7) * 4;
            float4 a4 = *(const float4*)(attn + ((size_t)(b * 32 + c)) * Sn + s0 + s4);
            const float* rsd = g_rstd + b * Sn + s0 + s4;
            a4.x *= rsd[0]; a4.y *= rsd[1]; a4.z *= rsd[2]; a4.w *= rsd[3];
            *(float4*)&a_sm[c][s4] = a4;
        }
        __syncthreads();
        #pragma unroll 8
        for (int si = 0; si < 32; si++) {
            float4 xv = *(const float4*)(g_xnew + (size_t)(b * Sn + s0 + si) * Dn + d);
            #pragma unroll
            for (int j = 0; j < 4; j++) {
                float av = a_sm[c0 + j][si];
                acc[j][0] += av * xv.x;
                acc[j][1] += av * xv.y;
                acc[j][2] += av * xv.z;
                acc[j][3] += av * xv.w;
            }
        }
        __syncthreads();
    }
    #pragma unroll
    for (int j = 0; j < 4; j++) {
        float4 o4 = make_float4(acc[j][0], acc[j][1], acc[j][2], acc[j][3]);
        *(float4*)(g_z + (size_t)(b * 32 + c0 + j) * Dn + d) = o4;
    }
}

// ===== o[b,n,j] = z[b,c,:]·Wvp[:,j] - Q*Gv[j] + P*Bv[j], j = h*32+hd =====
__global__ void __launch_bounds__(256)
k_o() {
    __shared__ float zs[16][512];
    int b = blockIdx.x, n = blockIdx.y;
    int t = threadIdx.x;
    int hh = t >> 5;                 // handles h = hh and hh+8
    int hd = t & 31;

    for (int idx = t; idx < 16 * 512; idx += 256) {
        int h = idx >> 9, d = idx & 511;
        zs[h][d] = g_z[(size_t)(b * 32 + h * 2 + n) * Dn + d];
    }
    __syncthreads();

    #pragma unroll
    for (int hi = 0; hi < 2; hi++) {
        int h = hh + hi * 8;
        int j = h * HDn + hd;
        float acc = 0.f;
        for (int d = 0; d < Dn; d++)
            acc += zs[h][d] * g_Wvp[(size_t)d * Dn + j];
        int c = h * 2 + n;
        float o = acc - g_Q[b * 32 + c] * g_Gv[j] + g_P[b * 32 + c] * g_Bv[j];
        g_o[(b * NCLSn + n) * Dn + j] = o;
    }
}

// ===== head: proj + LN + MLP -> logits, one block per (b,n) =====
__global__ void __launch_bounds__(256)
k_head(const float* __restrict__ Wproj, const float* __restrict__ bproj,
       const float* __restrict__ g2, const float* __restrict__ b2,
       const float* __restrict__ Wc1, const float* __restrict__ bc1,
       const float* __restrict__ Wc2, const float* __restrict__ bc2,
       float* __restrict__ out) {
    int bn = blockIdx.x;   // 0..63
    int t  = threadIdx.x;
    __shared__ float row[Dn];
    __shared__ float tmp[Dn];
    __shared__ float red[256];

    row[t]       = g_o[bn * Dn + t];
    row[t + 256] = g_o[bn * Dn + t + 256];
    __syncthreads();

    float a0 = 0.f, a1 = 0.f;
    for (int d = 0; d < Dn; d++) {
        float rv = row[d];
        a0 += rv * Wproj[d * Dn + t];
        a1 += rv * Wproj[d * Dn + t + 256];
    }
    tmp[t]       = a0 + bproj[t];
    tmp[t + 256] = a1 + bproj[t + 256];
    __syncthreads();

    float ps  = tmp[t] + tmp[t + 256];
    float pss = tmp[t] * tmp[t] + tmp[t + 256] * tmp[t + 256];
    red[t] = ps; __syncthreads();
    for (int o = 128; o > 0; o >>= 1) { if (t < o) red[t] += red[t + o]; __syncthreads(); }
    float mean = red[0] * (1.f / Dn);
    __syncthreads();
    red[t] = pss; __syncthreads();
    for (int o = 128; o > 0; o >>= 1) { if (t < o) red[t] += red[t + o]; __syncthreads(); }
    float var  = red[0] * (1.f / Dn) - mean * mean;
    float rstd = rsqrtf(var + 1e-5f);
    __syncthreads();

    row[t]       = (tmp[t] - mean) * rstd * g2[t] + b2[t];
    row[t + 256] = (tmp[t + 256] - mean) * rstd * g2[t + 256] + b2[t + 256];
    __syncthreads();

    float c0 = 0.f, c1 = 0.f;
    for (int d = 0; d < Dn; d++) {
        float rv = row[d];
        c0 += rv * Wc1[d * Dn + t];
        c1 += rv * Wc1[d * Dn + t + 256];
    }
    c0 = fmaxf(c0 + bc1[t], 0.f);
    c1 = fmaxf(c1 + bc1[t + 256], 0.f);
    float part = c0 * Wc2[t] + c1 * Wc2[t + 256];
    red[t] = part; __syncthreads();
    for (int o = 128; o > 0; o >>= 1) { if (t < o) red[t] += red[t + o]; __syncthreads(); }
    if (t == 0) out[bn] = red[0] + bc2[0];
}

// ===== launch =====
extern "C" void kernel_launch(void* const* d_in, const int* in_sizes, int n_in,
                              void* d_out, int out_size) {
    const float* x     = (const float*)d_in[0];
    const float* wave1 = (const float*)d_in[1];
    const float* wave2 = (const float*)d_in[2];
    const float* wave3 = (const float*)d_in[3];
    const float* Wp1   = (const float*)d_in[4];
    const float* bp1   = (const float*)d_in[5];
    const float* cls   = (const float*)d_in[6];
    const float* ln1g  = (const float*)d_in[7];
    const float* ln1b  = (const float*)d_in[8];
    const float* Wq    = (const float*)d_in[9];
    const float* Wkv   = (const float*)d_in[10];
    const float* Wproj = (const float*)d_in[11];
    const float* bproj = (const float*)d_in[12];
    const float* ln2g  = (const float*)d_in[13];
    const float* ln2b  = (const float*)d_in[14];
    const float* Wc1   = (const float*)d_in[15];
    const float* bc1   = (const float*)d_in[16];
    const float* Wc2   = (const float*)d_in[17];
    const float* bc2   = (const float*)d_in[18];
    float* out = (float*)d_out;
    float* attn = out + Bn * NCLSn;   // logits first, then attn [B,H,NCLS,S]

    // small prep
    k_prep_ksum<<<1, 512>>>(wave1, wave2, wave3);
    k_prep_q<<<4, 256>>>(cls, Wq);
    k_prep_A<<<512, 32>>>(Wkv, ln1g);
    k_prep_vec32<<<1, 1024>>>(ln1b);
    k_prep_wv<<<512, 512>>>(Wkv, ln1g);
    k_prep_vvec<<<4, 128>>>(Wkv, ln1b);

    // wavelet positional encoding
    k_conv<<<Rn / 8, 512>>>(x);
    k_gemm0<<<dim3(4, 512), 256>>>(Wp1, x, bp1);   // xnew = x + pos@Wp1 + bp1 (tf32 TC)
    k_rowstats<<<8192, 256>>>();                    // LN stats

    // attention
    k_scores<<<256, 256>>>(attn);                   // attn (LN folded)
    k_pq<<<Bn, 256>>>(attn);
    k_z<<<dim3(4, Bn), 256>>>(attn);
    k_o<<<dim3(Bn, NCLSn), 256>>>();

    // head -> logits
    k_head<<<64, 256>>>(Wproj, bproj, ln2g, ln2b, Wc1, bc1, Wc2, bc2, out);
}